// round 3
// baseline (speedup 1.0000x reference)
#include <cuda_runtime.h>
#include <cuda_fp16.h>

#define N_ANG 720
#define N_DET 1024
#define HIMG 512
#define WIMG 512
#define KSZ 11
#define NB 8

// Filtered sinogram, fp16, layout [angle][det_bin][batch0..7] -> 16B per bin.
__device__ __align__(16) __half g_h[N_ANG * N_DET * NB];

// ---------------------------------------------------------------------------
// Stage 1: causal K=11 cross-correlation. One thread = (angle a, 4 consecutive
// detector bins), all 8 batches. Window [4tx-12, 4tx+4) = 4 aligned float4
// per batch. Output: 4 uint4 stores (bin-packed 8 halves each).
// ---------------------------------------------------------------------------
__global__ void __launch_bounds__(256) conv_kernel(const float* __restrict__ x,
                                                   const float* __restrict__ w) {
    int tx = threadIdx.x;        // detector quad index 0..255
    int a  = blockIdx.x;         // angle

    float wk[KSZ];
#pragma unroll
    for (int k = 0; k < KSZ; ++k) wk[k] = __ldg(w + k);

    uint4 out[4];

#pragma unroll
    for (int bp = 0; bp < 4; ++bp) {          // batch pairs
        float acc[2][4];
#pragma unroll
        for (int s = 0; s < 2; ++s) {
            int b = bp * 2 + s;
            const float4* xb = reinterpret_cast<const float4*>(
                x + (size_t)b * (N_ANG * N_DET) + (size_t)a * N_DET);
            float win[16];
#pragma unroll
            for (int q = 0; q < 4; ++q) {
                int qi = tx - 3 + q;          // quad index into the row
                float4 v;
                if (qi >= 0) v = __ldg(xb + qi);
                else         v = make_float4(0.f, 0.f, 0.f, 0.f);
                win[q * 4 + 0] = v.x; win[q * 4 + 1] = v.y;
                win[q * 4 + 2] = v.z; win[q * 4 + 3] = v.w;
            }
#pragma unroll
            for (int di = 0; di < 4; ++di) {
                float acc_ = 0.f;
#pragma unroll
                for (int k = 0; k < KSZ; ++k)
                    acc_ = fmaf(wk[k], win[di + k + 2], acc_);  // x[d+k-10]
                acc[s][di] = acc_;
            }
        }
#pragma unroll
        for (int di = 0; di < 4; ++di) {
            __half2 h = __floats2half2_rn(acc[0][di], acc[1][di]);
            reinterpret_cast<unsigned int*>(&out[di])[bp] =
                *reinterpret_cast<unsigned int*>(&h);
        }
    }

    uint4* gp = reinterpret_cast<uint4*>(g_h) + ((size_t)a << 10) + (tx << 2);
#pragma unroll
    for (int di = 0; di < 4; ++di) gp[di] = out[di];
}

// ---------------------------------------------------------------------------
// Stage 2: backprojection. One thread = one pixel, all 8 batches.
// u in [150,873] -> no bounds checks. Floor via round-down magic-add; i0*16
// extracted with shifts (ALU pipe). Interp+accumulate fully in half2
// (2 HFMA2 per batch-pair per angle), flushed to fp32 every 8 angles.
// ---------------------------------------------------------------------------
__global__ void __launch_bounds__(256) bp_kernel(float* __restrict__ out) {
    __shared__ float2 trig[N_ANG];        // (cos/DS, sin/DS)

    const float DTH = 3.14159265358979323846f / (float)N_ANG;
    const float DX  = 2.0f / (float)HIMG;
    const float INV_DS = (float)N_DET / 4.0f;   // 256
    const float MAGIC  = 12582912.0f;           // 1.5 * 2^23... (2^23 used w/ RM)

    for (int a = threadIdx.x; a < N_ANG; a += blockDim.x) {
        float th = ((float)a + 0.5f) * DTH;
        float s, c;
        sincosf(th, &s, &c);
        trig[a] = make_float2(c * INV_DS, s * INV_DS);
    }
    __syncthreads();

    int tx = threadIdx.x;
    int j = (blockIdx.x << 3) + (tx & 7);
    int i = (blockIdx.y << 5) + (tx >> 3);
    float xc = fmaf((float)i + 0.5f, DX, -1.0f);
    float yc = fmaf((float)j + 0.5f, DX, -1.0f);

    float fa[NB];
#pragma unroll
    for (int b = 0; b < NB; ++b) fa[b] = 0.f;

    const char* gbase = reinterpret_cast<const char*>(g_h);
    const __half2 one2 = __float2half2_rn(1.0f);

#pragma unroll 1
    for (int a0 = 0; a0 < N_ANG; a0 += 8) {
        __half2 hacc0 = __float2half2_rn(0.f);
        __half2 hacc1 = hacc0, hacc2 = hacc0, hacc3 = hacc0;

#pragma unroll
        for (int k = 0; k < 8; ++k) {
            int a = a0 + k;
            float2 cs = trig[a];
            float u  = fmaf(xc, cs.x, fmaf(yc, cs.y, 511.5f));
            float t  = __fadd_rd(u, 8388608.0f);          // 2^23, round-down
            float fi = t - 8388608.0f;                     // exact floor(u)
            float f  = u - fi;                             // exact, in [0,1)
            unsigned bits = __float_as_uint(t);
            unsigned off  = (bits << 9) >> 5;              // i0 * 16 bytes

            const uint4* p = reinterpret_cast<const uint4*>(
                gbase + ((size_t)a << 14) + off);
            uint4 lo = __ldg(p);
            uint4 hi = __ldg(p + 1);

            __half2 f2   = __float2half2_rn(f);
            __half2 omf2 = __hsub2(one2, f2);

            hacc0 = __hfma2(f2, *reinterpret_cast<__half2*>(&hi.x),
                    __hfma2(omf2, *reinterpret_cast<__half2*>(&lo.x), hacc0));
            hacc1 = __hfma2(f2, *reinterpret_cast<__half2*>(&hi.y),
                    __hfma2(omf2, *reinterpret_cast<__half2*>(&lo.y), hacc1));
            hacc2 = __hfma2(f2, *reinterpret_cast<__half2*>(&hi.z),
                    __hfma2(omf2, *reinterpret_cast<__half2*>(&lo.z), hacc2));
            hacc3 = __hfma2(f2, *reinterpret_cast<__half2*>(&hi.w),
                    __hfma2(omf2, *reinterpret_cast<__half2*>(&lo.w), hacc3));
        }
        float2 v;
        v = __half22float2(hacc0); fa[0] += v.x; fa[1] += v.y;
        v = __half22float2(hacc1); fa[2] += v.x; fa[3] += v.y;
        v = __half22float2(hacc2); fa[4] += v.x; fa[5] += v.y;
        v = __half22float2(hacc3); fa[6] += v.x; fa[7] += v.y;
    }

    int p = i * WIMG + j;
#pragma unroll
    for (int b = 0; b < NB; ++b)
        out[b * (HIMG * WIMG) + p] = fa[b] * DTH;
}

// ---------------------------------------------------------------------------
extern "C" void kernel_launch(void* const* d_in, const int* in_sizes, int n_in,
                              void* d_out, int out_size) {
    const float* x = (const float*)d_in[0];   // [8,1,720,1024]
    const float* w = (const float*)d_in[1];   // [1,1,1,11]
    float* out = (float*)d_out;               // [8,1,512,512]

    conv_kernel<<<N_ANG, 256>>>(x, w);
    dim3 grid(WIMG / 8, HIMG / 32);           // (64, 16)
    bp_kernel<<<grid, 256>>>(out);
}

// round 4
// speedup vs baseline: 1.4527x; 1.4527x over previous
#include <cuda_runtime.h>
#include <cuda_fp16.h>

#define N_ANG 720
#define N_DET 1024
#define HIMG 512
#define WIMG 512
#define KSZ 11
#define NB 8

// Filtered sinogram, fp16, layout [angle][det_bin][batch0..7] -> 16B per bin.
__device__ __align__(16) __half g_h[N_ANG * N_DET * NB];

// ---------------------------------------------------------------------------
// Stage 1: causal K=11 cross-correlation. One thread = (angle a, 4 consecutive
// detector bins), all 8 batches. Window [4tx-12, 4tx+4) = 4 aligned float4
// per batch. Output: 4 uint4 stores (bin-packed 8 halves each).
// ---------------------------------------------------------------------------
__global__ void __launch_bounds__(256) conv_kernel(const float* __restrict__ x,
                                                   const float* __restrict__ w) {
    int tx = threadIdx.x;        // detector quad index 0..255
    int a  = blockIdx.x;         // angle

    float wk[KSZ];
#pragma unroll
    for (int k = 0; k < KSZ; ++k) wk[k] = __ldg(w + k);

    uint4 out[4];

#pragma unroll
    for (int bp = 0; bp < 4; ++bp) {          // batch pairs
        float acc[2][4];
#pragma unroll
        for (int s = 0; s < 2; ++s) {
            int b = bp * 2 + s;
            const float4* xb = reinterpret_cast<const float4*>(
                x + (size_t)b * (N_ANG * N_DET) + (size_t)a * N_DET);
            float win[16];
#pragma unroll
            for (int q = 0; q < 4; ++q) {
                int qi = tx - 3 + q;          // quad index into the row
                float4 v;
                if (qi >= 0) v = __ldg(xb + qi);
                else         v = make_float4(0.f, 0.f, 0.f, 0.f);
                win[q * 4 + 0] = v.x; win[q * 4 + 1] = v.y;
                win[q * 4 + 2] = v.z; win[q * 4 + 3] = v.w;
            }
#pragma unroll
            for (int di = 0; di < 4; ++di) {
                float acc_ = 0.f;
#pragma unroll
                for (int k = 0; k < KSZ; ++k)
                    acc_ = fmaf(wk[k], win[di + k + 2], acc_);  // x[d+k-10]
                acc[s][di] = acc_;
            }
        }
#pragma unroll
        for (int di = 0; di < 4; ++di) {
            __half2 h = __floats2half2_rn(acc[0][di], acc[1][di]);
            reinterpret_cast<unsigned int*>(&out[di])[bp] =
                *reinterpret_cast<unsigned int*>(&h);
        }
    }

    uint4* gp = reinterpret_cast<uint4*>(g_h) + ((size_t)a << 10) + (tx << 2);
#pragma unroll
    for (int di = 0; di < 4; ++di) gp[di] = out[di];
}

// ---------------------------------------------------------------------------
// Stage 2: backprojection. One thread = one pixel, all 8 batches.
// u in [150,873] -> no bounds checks; floor via round-down magic-add (ALU).
// SPLIT half2 accumulators: accF += f*hi, accL += (1-f)*lo -> 8 independent
// 1-HFMA2-per-angle chains (4-cyc RAW each) instead of 4 chains of 2.
// Flushed to fp32 every 8 angles.
// ---------------------------------------------------------------------------
__global__ void __launch_bounds__(256) bp_kernel(float* __restrict__ out) {
    __shared__ float2 trig[N_ANG];        // (cos/DS, sin/DS)

    const float DTH = 3.14159265358979323846f / (float)N_ANG;
    const float DX  = 2.0f / (float)HIMG;
    const float INV_DS = (float)N_DET / 4.0f;   // 256

    for (int a = threadIdx.x; a < N_ANG; a += blockDim.x) {
        float th = ((float)a + 0.5f) * DTH;
        float s, c;
        sincosf(th, &s, &c);
        trig[a] = make_float2(c * INV_DS, s * INV_DS);
    }
    __syncthreads();

    int tx = threadIdx.x;
    int j = (blockIdx.x << 3) + (tx & 7);
    int i = (blockIdx.y << 5) + (tx >> 3);
    float xc = fmaf((float)i + 0.5f, DX, -1.0f);
    float yc = fmaf((float)j + 0.5f, DX, -1.0f);

    float fa[NB];
#pragma unroll
    for (int b = 0; b < NB; ++b) fa[b] = 0.f;

    const char* gbase = reinterpret_cast<const char*>(g_h);
    const __half2 one2 = __float2half2_rn(1.0f);
    const __half2 zero2 = __float2half2_rn(0.0f);

#pragma unroll 1
    for (int a0 = 0; a0 < N_ANG; a0 += 8) {
        __half2 accF0 = zero2, accF1 = zero2, accF2 = zero2, accF3 = zero2;
        __half2 accL0 = zero2, accL1 = zero2, accL2 = zero2, accL3 = zero2;

#pragma unroll
        for (int k = 0; k < 8; ++k) {
            int a = a0 + k;
            float2 cs = trig[a];
            float u  = fmaf(xc, cs.x, fmaf(yc, cs.y, 511.5f));
            float t  = __fadd_rd(u, 8388608.0f);          // 2^23, round-down
            float fi = t - 8388608.0f;                     // exact floor(u)
            float f  = u - fi;                             // exact, in [0,1)
            unsigned bits = __float_as_uint(t);
            unsigned off  = (bits << 9) >> 5;              // i0 * 16 bytes

            const uint4* p = reinterpret_cast<const uint4*>(
                gbase + ((size_t)a << 14) + off);
            uint4 lo = __ldg(p);
            uint4 hi = __ldg(p + 1);

            __half2 f2   = __float2half2_rn(f);
            __half2 omf2 = __hsub2(one2, f2);

            accF0 = __hfma2(f2,   *reinterpret_cast<__half2*>(&hi.x), accF0);
            accL0 = __hfma2(omf2, *reinterpret_cast<__half2*>(&lo.x), accL0);
            accF1 = __hfma2(f2,   *reinterpret_cast<__half2*>(&hi.y), accF1);
            accL1 = __hfma2(omf2, *reinterpret_cast<__half2*>(&lo.y), accL1);
            accF2 = __hfma2(f2,   *reinterpret_cast<__half2*>(&hi.z), accF2);
            accL2 = __hfma2(omf2, *reinterpret_cast<__half2*>(&lo.z), accL2);
            accF3 = __hfma2(f2,   *reinterpret_cast<__half2*>(&hi.w), accF3);
            accL3 = __hfma2(omf2, *reinterpret_cast<__half2*>(&lo.w), accL3);
        }
        float2 v;
        __half2 s0 = __hadd2(accF0, accL0);
        __half2 s1 = __hadd2(accF1, accL1);
        __half2 s2 = __hadd2(accF2, accL2);
        __half2 s3 = __hadd2(accF3, accL3);
        v = __half22float2(s0); fa[0] += v.x; fa[1] += v.y;
        v = __half22float2(s1); fa[2] += v.x; fa[3] += v.y;
        v = __half22float2(s2); fa[4] += v.x; fa[5] += v.y;
        v = __half22float2(s3); fa[6] += v.x; fa[7] += v.y;
    }

    int p = i * WIMG + j;
#pragma unroll
    for (int b = 0; b < NB; ++b)
        out[b * (HIMG * WIMG) + p] = fa[b] * DTH;
}

// ---------------------------------------------------------------------------
extern "C" void kernel_launch(void* const* d_in, const int* in_sizes, int n_in,
                              void* d_out, int out_size) {
    const float* x = (const float*)d_in[0];   // [8,1,720,1024]
    const float* w = (const float*)d_in[1];   // [1,1,1,11]
    float* out = (float*)d_out;               // [8,1,512,512]

    conv_kernel<<<N_ANG, 256>>>(x, w);
    dim3 grid(WIMG / 8, HIMG / 32);           // (64, 16)
    bp_kernel<<<grid, 256>>>(out);
}